// round 12
// baseline (speedup 1.0000x reference)
#include <cuda_runtime.h>
#include <cuda_bf16.h>
#include <cuda_fp16.h>
#include <cstdint>
#include <cstddef>

// Problem constants
#define NN 10000
#define EE 40000
#define DIN 11
#define DD 64
#define FEA 4
#define LL 4
#define BB 512
#define MM 3
#define DH 128          // 2*D, edge-MLP hidden
#define DSQ 4096        // D*D
#define EPAD 128        // padded edge rows for GEMM tile overrun

// ---------------- device scratch (static globals; no allocation) ----------------
__device__ __half g_EWh[(size_t)EE * DSQ];          // 327 MB: per-edge weight matrices (fp16)
__device__ __half g_hidh[(size_t)(EE + EPAD) * DH]; // hid hi (fp16)
__device__ __half g_Wn2Th[(size_t)DSQ * DH];        // Wn2 transposed [n][k] hi
__device__ __half g_Wn2Tl[(size_t)DSQ * DH];        // Wn2 transposed [n][k] lo
__device__ float g_h[NN * DD];               // node features
__device__ float g_aggr[NN * DD];            // scatter accumulator
__device__ float g_escore[NN];               // attention logits
__device__ int   g_segstart[BB + 1];

__device__ __forceinline__ float sigf(float x) { return 1.f / (1.f + expf(-x)); }

__device__ __forceinline__ void mma_f16(float* c, const uint32_t* a, uint32_t b0, uint32_t b1) {
    asm volatile(
        "mma.sync.aligned.m16n8k16.row.col.f32.f16.f16.f32 "
        "{%0,%1,%2,%3}, {%4,%5,%6,%7}, {%8,%9}, {%0,%1,%2,%3};"
        : "+f"(c[0]), "+f"(c[1]), "+f"(c[2]), "+f"(c[3])
        : "r"(a[0]), "r"(a[1]), "r"(a[2]), "r"(a[3]), "r"(b0), "r"(b1));
}
__device__ __forceinline__ void ldmx4(uint32_t* r, uint32_t addr) {
    asm volatile("ldmatrix.sync.aligned.m8n8.x4.shared.b16 {%0,%1,%2,%3}, [%4];"
                 : "=r"(r[0]), "=r"(r[1]), "=r"(r[2]), "=r"(r[3]) : "r"(addr));
}

// ================= fused prologue: init + seg + h0 + hid + Wn2 transpose/split ===========
__global__ void prologue_kernel(const float* __restrict__ x, const float* __restrict__ ea,
                                const int* __restrict__ batch,
                                const float* __restrict__ W0, const float* __restrict__ b0,
                                const float* __restrict__ Wn1, const float* __restrict__ bn1,
                                const float* __restrict__ Wn2) {
    int idx = blockIdx.x * 256 + threadIdx.x;
    if (idx < EE * DH) {                               // hid = silu(ea@Wn1+bn1) -> fp16 hi
        int e = idx >> 7, k = idx & 127;
        float4 a = *(const float4*)&ea[e * 4];
        float v = bn1[k] + a.x * Wn1[k] + a.y * Wn1[DH + k] + a.z * Wn1[2 * DH + k]
                + a.w * Wn1[3 * DH + k];
        v = v * sigf(v);
        g_hidh[idx] = __float2half_rn(v);
    }
    if (idx < DSQ * DH) {                              // Wn2^T hi/lo
        int n = idx >> 7, k = idx & 127;
        float v = Wn2[(size_t)k * DSQ + n];
        __half hh = __float2half_rn(v);
        g_Wn2Th[idx] = hh;
        g_Wn2Tl[idx] = __float2half_rn(v - __half2float(hh));
    }
    if (idx < NN * DD) {                               // aggr=0 and h0 = x@W0+b0
        g_aggr[idx] = 0.f;
        int n = idx >> 6, f = idx & 63;
        float acc = b0[f];
#pragma unroll
        for (int d = 0; d < DIN; ++d) acc += x[n * DIN + d] * W0[d * DD + f];
        g_h[idx] = acc;
    }
    if (idx < EPAD * DH) g_hidh[(size_t)EE * DH + idx] = __float2half(0.f);
    if (idx < NN) {                                    // segment starts
        int bcur = batch[idx];
        int bprev = (idx == 0) ? -1 : batch[idx - 1];
        for (int g = bprev + 1; g <= bcur; ++g) g_segstart[g] = idx;
        if (idx == NN - 1)
            for (int g = bcur + 1; g <= BB; ++g) g_segstart[g] = NN;
    }
}

// ================= EW GEMM: m16n8k16 fp16 HMMA, 2-term split (AhBh + AhBl), ldmatrix ======
// C[E,4096] = hid[E,128] @ Wn2[128,4096] + bn2. CTA tile 128x128, K in 2 chunks of 64.
// 8 warps: 4 along M (32 rows) x 2 along N (64 cols). Smem rows: 72 halfs (144B) stride.
#define SAH_B 0
#define SBH_B 18432
#define SBL_B 36864
#define SBIAS_B 55296
#define EW_SMEM_BYTES (55296 + 512)

__global__ void __launch_bounds__(256) ew_gemm_mma(const float* __restrict__ bn2) {
    extern __shared__ char sm[];
    __half* smh = (__half*)sm;
    const int tid = threadIdx.x;
    const int wid = tid >> 5, lane = tid & 31;
    const int g = lane >> 2, tig = lane & 3;
    const int wm = wid & 3, wn = wid >> 2;             // warp position: 4 x 2
    const int n0 = blockIdx.x * 128;
    const int m0 = blockIdx.y * 128;

    if (tid < 128) ((float*)(sm + SBIAS_B))[tid] = bn2[n0 + tid];

    // per-lane ldmatrix address components
    const int rowA = (lane & 7) + ((lane >> 3) & 1) * 8;
    const int kAoff = ((lane >> 4) & 1) * 8;           // halfs
    const int rowB = (lane & 7) + ((lane >> 4) & 1) * 8;
    const int kBoff = ((lane >> 3) & 1) * 8;

    const uint32_t smb = (uint32_t)__cvta_generic_to_shared(sm);
    const uint32_t aBase  = smb + SAH_B + (wm * 32 + rowA) * 144 + kAoff * 2;
    const uint32_t bBaseH = smb + SBH_B + (wn * 64 + rowB) * 144 + kBoff * 2;
    const uint32_t bBaseL = smb + SBL_B + (wn * 64 + rowB) * 144 + kBoff * 2;

    float C[2][8][4];
#pragma unroll
    for (int mt = 0; mt < 2; ++mt)
#pragma unroll
        for (int nt = 0; nt < 8; ++nt)
#pragma unroll
            for (int r = 0; r < 4; ++r) C[mt][nt][r] = 0.f;

#pragma unroll
    for (int kc = 0; kc < 2; ++kc) {
        // ---- fill (q-outer: conflict-free STS.128 and ldmatrix) ----
#pragma unroll
        for (int i = 0; i < 4; ++i) {
            int idx = tid + i * 256;                   // 1024 uint4
            int row = idx & 127, q = idx >> 7;         // q: 8-half chunk 0..7
            size_t ga = (size_t)(m0 + row) * DH + kc * 64 + q * 8;
            *(uint4*)(smh + row * 72 + q * 8) = *(const uint4*)(g_hidh + ga);
        }
#pragma unroll
        for (int i = 0; i < 4; ++i) {
            int idx = tid + i * 256;
            int row = idx & 127, q = idx >> 7;
            size_t gb = (size_t)(n0 + row) * DH + kc * 64 + q * 8;
            int so = row * 72 + q * 8;
            *(uint4*)((__half*)(sm + SBH_B) + so) = *(const uint4*)(g_Wn2Th + gb);
            *(uint4*)((__half*)(sm + SBL_B) + so) = *(const uint4*)(g_Wn2Tl + gb);
        }
        __syncthreads();

#pragma unroll
        for (int k16 = 0; k16 < 4; ++k16) {
            uint32_t ah[2][4];
#pragma unroll
            for (int mt = 0; mt < 2; ++mt)
                ldmx4(ah[mt], aBase + mt * (16 * 144) + k16 * 32);
#pragma unroll
            for (int pair = 0; pair < 4; ++pair) {
                uint32_t bh[4], bl[4];
                ldmx4(bh, bBaseH + pair * (16 * 144) + k16 * 32);
                ldmx4(bl, bBaseL + pair * (16 * 144) + k16 * 32);
#pragma unroll
                for (int mt = 0; mt < 2; ++mt) {
                    mma_f16(C[mt][2 * pair],     ah[mt], bh[0], bh[1]);
                    mma_f16(C[mt][2 * pair],     ah[mt], bl[0], bl[1]);
                    mma_f16(C[mt][2 * pair + 1], ah[mt], bh[2], bh[3]);
                    mma_f16(C[mt][2 * pair + 1], ah[mt], bl[2], bl[3]);
                }
            }
        }
        __syncthreads();
    }

    // ---- epilogue: bias add, fp16 store ----
    const float* bias = (const float*)(sm + SBIAS_B);
#pragma unroll
    for (int mt = 0; mt < 2; ++mt) {
        int r0 = m0 + wm * 32 + mt * 16 + g;
        int r1 = r0 + 8;
#pragma unroll
        for (int nt = 0; nt < 8; ++nt) {
            int c = wn * 64 + nt * 8 + tig * 2;        // local col, even
            float bz0 = bias[c], bz1 = bias[c + 1];
            if (r0 < EE)
                *(__half2*)(g_EWh + (size_t)r0 * DSQ + n0 + c) =
                    __floats2half2_rn(C[mt][nt][0] + bz0, C[mt][nt][1] + bz1);
            if (r1 < EE)
                *(__half2*)(g_EWh + (size_t)r1 * DSQ + n0 + c) =
                    __floats2half2_rn(C[mt][nt][2] + bz0, C[mt][nt][3] + bz1);
        }
    }
}

// ---------------- per-layer: msg = h[src] @ EW[e] (fp16), scatter-add into aggr ---------
__global__ void conv_msg_kernel(const int* __restrict__ ei) {
    __shared__ float sh[8][64];
    int sub = threadIdx.x >> 5;                        // 8 edges / block, 1 warp each
    int t = threadIdx.x & 31;
    int e = blockIdx.x * 8 + sub;
    if (e >= EE) return;
    int src = ei[e];
    int dst = ei[EE + e];
    sh[sub][t] = g_h[src * DD + t];
    sh[sub][32 + t] = g_h[src * DD + 32 + t];
    __syncwarp();
    const __half2* ew2 = (const __half2*)(g_EWh + (size_t)e * DSQ) + t;
    float a0 = 0.f, a1 = 0.f;
#pragma unroll
    for (int d = 0; d < 64; ++d) {
        float2 w = __half22float2(ew2[d * 32]);
        float hv = sh[sub][d];
        a0 += hv * w.x;
        a1 += hv * w.y;
    }
    atomicAdd(&g_aggr[dst * DD + 2 * t], a0);
    atomicAdd(&g_aggr[dst * DD + 2 * t + 1], a1);
}

// ---------------- per-layer: h += aggr + h@root[l] + bias[l]; re-zero aggr ----------------
__global__ void h_update_kernel(const float* __restrict__ root_l,
                                const float* __restrict__ bias_l) {
    __shared__ float sh[4][64];
    int sub = threadIdx.x >> 6;
    int f = threadIdx.x & 63;
    int n = blockIdx.x * 4 + sub;
    sh[sub][f] = g_h[n * DD + f];
    __syncthreads();
    float acc = 0.f;
#pragma unroll 16
    for (int d = 0; d < 64; ++d) acc += sh[sub][d] * root_l[d * DD + f];
    g_h[n * DD + f] = sh[sub][f] + g_aggr[n * DD + f] + acc + bias_l[f];
    g_aggr[n * DD + f] = 0.f;
}

// ================= fused Set2Set (M steps of LSTM+escore+pool) + output MLP ==============
// One block per graph; all state lives in smem. 256 threads.
__global__ void __launch_bounds__(256) set2set_out_kernel(
    const float* __restrict__ Wih, const float* __restrict__ Whh,
    const float* __restrict__ bvec,
    const float* __restrict__ Wo1, const float* __restrict__ bo1,
    const float* __restrict__ Wo2, const float* __restrict__ bo2,
    float* __restrict__ out) {
    int b = blockIdx.x, t = threadIdx.x;
    int warp = t >> 5, lane = t & 31;
    __shared__ float sq[128], shh[64], scs[64], gs[256], red[256], r2[256];
    const int s = g_segstart[b], e = g_segstart[b + 1];

    if (t < 128) sq[t] = 0.f;
    if (t < 64) { shh[t] = 0.f; scs[t] = 0.f; }
    __syncthreads();

    for (int m = 0; m < MM; ++m) {
        // ---- LSTM gates ----
        for (int gi = warp; gi < 256; gi += 8) {
            float acc = 0.f;
#pragma unroll
            for (int k = 0; k < 4; ++k) acc += sq[lane + k * 32] * Wih[gi * 128 + lane + k * 32];
#pragma unroll
            for (int k = 0; k < 2; ++k) acc += shh[lane + k * 32] * Whh[gi * 64 + lane + k * 32];
#pragma unroll
            for (int o = 16; o > 0; o >>= 1) acc += __shfl_down_sync(0xffffffffu, acc, o);
            if (lane == 0) gs[gi] = acc + bvec[gi];
        }
        __syncthreads();
        if (t < 64) {
            float gi = gs[t], gf = gs[64 + t], gg = gs[128 + t], go = gs[192 + t];
            float c = sigf(gf) * scs[t] + sigf(gi) * tanhf(gg);
            scs[t] = c;
            shh[t] = sigf(go) * tanhf(c);
        }
        __syncthreads();
        // ---- escore: e[n] = h[n] . q ----
        for (int n = s + warp; n < e; n += 8) {
            float acc = g_h[n * 64 + lane] * shh[lane] + g_h[n * 64 + 32 + lane] * shh[32 + lane];
#pragma unroll
            for (int o = 16; o > 0; o >>= 1) acc += __shfl_down_sync(0xffffffffu, acc, o);
            if (lane == 0) g_escore[n] = acc;
        }
        __syncthreads();
        // ---- pool: per-graph softmax, r = sum a*h ----
        float mx = -3.4e38f;
        for (int n = s + t; n < e; n += 256) mx = fmaxf(mx, g_escore[n]);
        red[t] = mx;
        __syncthreads();
        for (int o = 128; o > 0; o >>= 1) { if (t < o) red[t] = fmaxf(red[t], red[t + o]); __syncthreads(); }
        mx = red[0];
        __syncthreads();
        float den = 0.f;
        for (int n = s + t; n < e; n += 256) den += expf(g_escore[n] - mx);
        red[t] = den;
        __syncthreads();
        for (int o = 128; o > 0; o >>= 1) { if (t < o) red[t] += red[t + o]; __syncthreads(); }
        float inv = (e > s) ? (1.f / red[0]) : 0.f;
        __syncthreads();
        int f = t & 63, grp = t >> 6;
        float rf = 0.f;
        for (int n = s + grp; n < e; n += 4) rf += expf(g_escore[n] - mx) * g_h[n * 64 + f];
        r2[t] = rf;
        __syncthreads();
        if (t < 64) {
            float rv = (r2[t] + r2[64 + t] + r2[128 + t] + r2[192 + t]) * inv;
            sq[t] = shh[t];
            sq[64 + t] = rv;
        }
        __syncthreads();
    }
    // ---- out = silu(q_star @ Wo1 + bo1) @ Wo2 + bo2 ----
    if (t < 64) {
        float acc = bo1[t];
#pragma unroll 16
        for (int k = 0; k < 128; ++k) acc += sq[k] * Wo1[k * 64 + t];
        float sv = acc * sigf(acc);
        red[t] = sv * Wo2[t];
    }
    __syncthreads();
    for (int o = 32; o > 0; o >>= 1) { if (t < o) red[t] += red[t + o]; __syncthreads(); }
    if (t == 0) out[b] = red[0] + bo2[0];
}

// ---------------- launch ----------------
extern "C" void kernel_launch(void* const* d_in, const int* in_sizes, int n_in,
                              void* d_out, int out_size) {
    const float* x         = (const float*)d_in[0];
    const int*   edgeidx   = (const int*)d_in[1];
    const float* edge_attr = (const float*)d_in[2];
    const int*   batch     = (const int*)d_in[3];
    const float* W0        = (const float*)d_in[4];
    const float* b0        = (const float*)d_in[5];
    const float* Wn1       = (const float*)d_in[6];
    const float* bn1       = (const float*)d_in[7];
    const float* Wn2       = (const float*)d_in[8];
    const float* bn2       = (const float*)d_in[9];
    const float* root      = (const float*)d_in[10];
    const float* conv_bias = (const float*)d_in[11];
    const float* lstm_Wih  = (const float*)d_in[12];
    const float* lstm_Whh  = (const float*)d_in[13];
    const float* lstm_b    = (const float*)d_in[14];
    const float* Wo1       = (const float*)d_in[15];
    const float* bo1       = (const float*)d_in[16];
    const float* Wo2       = (const float*)d_in[17];
    const float* bo2       = (const float*)d_in[18];
    float* out = (float*)d_out;

    cudaFuncSetAttribute(ew_gemm_mma, cudaFuncAttributeMaxDynamicSharedMemorySize,
                         EW_SMEM_BYTES);

    prologue_kernel<<<(EE * DH + 255) / 256, 256>>>(x, edge_attr, batch, W0, b0,
                                                    Wn1, bn1, Wn2);

    dim3 ggrid(32, (EE + 127) / 128);                  // 32 n-blocks x 313 m-blocks
    ew_gemm_mma<<<ggrid, 256, EW_SMEM_BYTES>>>(bn2);

    for (int l = 0; l < LL; ++l) {
        conv_msg_kernel<<<(EE + 7) / 8, 256>>>(edgeidx);
        h_update_kernel<<<(NN + 3) / 4, 256>>>(root + (size_t)l * DSQ, conv_bias + l * DD);
    }

    set2set_out_kernel<<<BB, 256>>>(lstm_Wih, lstm_Whh, lstm_b, Wo1, bo1, Wo2, bo2, out);
}

// round 13
// speedup vs baseline: 1.1069x; 1.1069x over previous
#include <cuda_runtime.h>
#include <cuda_bf16.h>
#include <cuda_fp16.h>
#include <cstdint>
#include <cstddef>

// Problem constants
#define NN 10000
#define EE 40000
#define DIN 11
#define DD 64
#define FEA 4
#define LL 4
#define BB 512
#define MM 3
#define DH 128          // 2*D, edge-MLP hidden
#define DSQ 4096        // D*D
#define EPAD 128        // padded edge rows for GEMM tile overrun

// ---------------- device scratch (static globals; no allocation) ----------------
__device__ __half g_EWh[(size_t)EE * DSQ];          // 327 MB: per-edge weight matrices (fp16)
__device__ __half g_hidh[(size_t)(EE + EPAD) * DH]; // hid hi (fp16)
__device__ __half g_Wn2Th[(size_t)DSQ * DH];        // Wn2 transposed [n][k] hi
__device__ __half g_Wn2Tl[(size_t)DSQ * DH];        // Wn2 transposed [n][k] lo
__device__ float g_h[NN * DD];               // node features
__device__ float g_aggr[NN * DD];            // scatter accumulator
__device__ float g_escore[NN];               // attention logits
__device__ int   g_segstart[BB + 1];

__device__ __forceinline__ float sigf(float x) { return 1.f / (1.f + expf(-x)); }

__device__ __forceinline__ void mma_f16(float* c, const uint32_t* a, uint32_t b0, uint32_t b1) {
    asm volatile(
        "mma.sync.aligned.m16n8k16.row.col.f32.f16.f16.f32 "
        "{%0,%1,%2,%3}, {%4,%5,%6,%7}, {%8,%9}, {%0,%1,%2,%3};"
        : "+f"(c[0]), "+f"(c[1]), "+f"(c[2]), "+f"(c[3])
        : "r"(a[0]), "r"(a[1]), "r"(a[2]), "r"(a[3]), "r"(b0), "r"(b1));
}
__device__ __forceinline__ void ldmx4(uint32_t* r, uint32_t addr) {
    asm volatile("ldmatrix.sync.aligned.m8n8.x4.shared.b16 {%0,%1,%2,%3}, [%4];"
                 : "=r"(r[0]), "=r"(r[1]), "=r"(r[2]), "=r"(r[3]) : "r"(addr));
}

// ================= fused prologue: init + seg + h0 + hid + Wn2 transpose/split ===========
__global__ void prologue_kernel(const float* __restrict__ x, const float* __restrict__ ea,
                                const int* __restrict__ batch,
                                const float* __restrict__ W0, const float* __restrict__ b0,
                                const float* __restrict__ Wn1, const float* __restrict__ bn1,
                                const float* __restrict__ Wn2) {
    int idx = blockIdx.x * 256 + threadIdx.x;
    if (idx < EE * DH) {                               // hid = silu(ea@Wn1+bn1) -> fp16 hi
        int e = idx >> 7, k = idx & 127;
        float4 a = *(const float4*)&ea[e * 4];
        float v = bn1[k] + a.x * Wn1[k] + a.y * Wn1[DH + k] + a.z * Wn1[2 * DH + k]
                + a.w * Wn1[3 * DH + k];
        v = v * sigf(v);
        g_hidh[idx] = __float2half_rn(v);
    }
    if (idx < DSQ * DH) {                              // Wn2^T hi/lo
        int n = idx >> 7, k = idx & 127;
        float v = Wn2[(size_t)k * DSQ + n];
        __half hh = __float2half_rn(v);
        g_Wn2Th[idx] = hh;
        g_Wn2Tl[idx] = __float2half_rn(v - __half2float(hh));
    }
    if (idx < NN * DD) {                               // aggr=0 and h0 = x@W0+b0
        g_aggr[idx] = 0.f;
        int n = idx >> 6, f = idx & 63;
        float acc = b0[f];
#pragma unroll
        for (int d = 0; d < DIN; ++d) acc += x[n * DIN + d] * W0[d * DD + f];
        g_h[idx] = acc;
    }
    if (idx < EPAD * DH) g_hidh[(size_t)EE * DH + idx] = __float2half(0.f);
    if (idx < NN) {                                    // segment starts
        int bcur = batch[idx];
        int bprev = (idx == 0) ? -1 : batch[idx - 1];
        for (int g = bprev + 1; g <= bcur; ++g) g_segstart[g] = idx;
        if (idx == NN - 1)
            for (int g = bcur + 1; g <= BB; ++g) g_segstart[g] = NN;
    }
}

// ================= EW GEMM: m16n8k16 fp16 HMMA, 2-term split (AhBh + AhBl), ldmatrix ======
// C[E,4096] = hid[E,128] @ Wn2[128,4096] + bn2. CTA tile 128x128, K in 2 chunks of 64.
// 8 warps: 4 along M (32 rows) x 2 along N (64 cols). Smem rows: 72 halfs (144B) stride.
// __launch_bounds__(256, 2) is LOAD-BEARING: it caps regs at 128 so 2 CTAs/SM co-reside
// (smem 55.8 KB/CTA also fits 2); at occupancy 1 the fill->sync->MMA phases serialize.
#define SAH_B 0
#define SBH_B 18432
#define SBL_B 36864
#define SBIAS_B 55296
#define EW_SMEM_BYTES (55296 + 512)

__global__ void __launch_bounds__(256, 2) ew_gemm_mma(const float* __restrict__ bn2) {
    extern __shared__ char sm[];
    __half* smh = (__half*)sm;
    const int tid = threadIdx.x;
    const int wid = tid >> 5, lane = tid & 31;
    const int g = lane >> 2, tig = lane & 3;
    const int wm = wid & 3, wn = wid >> 2;             // warp position: 4 x 2
    const int n0 = blockIdx.x * 128;
    const int m0 = blockIdx.y * 128;

    if (tid < 128) ((float*)(sm + SBIAS_B))[tid] = bn2[n0 + tid];

    // per-lane ldmatrix address components
    const int rowA = (lane & 7) + ((lane >> 3) & 1) * 8;
    const int kAoff = ((lane >> 4) & 1) * 8;           // halfs
    const int rowB = (lane & 7) + ((lane >> 4) & 1) * 8;
    const int kBoff = ((lane >> 3) & 1) * 8;

    const uint32_t smb = (uint32_t)__cvta_generic_to_shared(sm);
    const uint32_t aBase  = smb + SAH_B + (wm * 32 + rowA) * 144 + kAoff * 2;
    const uint32_t bBaseH = smb + SBH_B + (wn * 64 + rowB) * 144 + kBoff * 2;
    const uint32_t bBaseL = smb + SBL_B + (wn * 64 + rowB) * 144 + kBoff * 2;

    float C[2][8][4];
#pragma unroll
    for (int mt = 0; mt < 2; ++mt)
#pragma unroll
        for (int nt = 0; nt < 8; ++nt)
#pragma unroll
            for (int r = 0; r < 4; ++r) C[mt][nt][r] = 0.f;

#pragma unroll
    for (int kc = 0; kc < 2; ++kc) {
        // ---- fill (q-outer: conflict-free STS.128 and ldmatrix) ----
#pragma unroll
        for (int i = 0; i < 4; ++i) {
            int idx = tid + i * 256;                   // 1024 uint4
            int row = idx & 127, q = idx >> 7;         // q: 8-half chunk 0..7
            size_t ga = (size_t)(m0 + row) * DH + kc * 64 + q * 8;
            *(uint4*)(smh + row * 72 + q * 8) = *(const uint4*)(g_hidh + ga);
        }
#pragma unroll
        for (int i = 0; i < 4; ++i) {
            int idx = tid + i * 256;
            int row = idx & 127, q = idx >> 7;
            size_t gb = (size_t)(n0 + row) * DH + kc * 64 + q * 8;
            int so = row * 72 + q * 8;
            *(uint4*)((__half*)(sm + SBH_B) + so) = *(const uint4*)(g_Wn2Th + gb);
            *(uint4*)((__half*)(sm + SBL_B) + so) = *(const uint4*)(g_Wn2Tl + gb);
        }
        __syncthreads();

#pragma unroll
        for (int k16 = 0; k16 < 4; ++k16) {
            uint32_t ah[2][4];
#pragma unroll
            for (int mt = 0; mt < 2; ++mt)
                ldmx4(ah[mt], aBase + mt * (16 * 144) + k16 * 32);
#pragma unroll
            for (int pair = 0; pair < 4; ++pair) {
                uint32_t bh[4], bl[4];
                ldmx4(bh, bBaseH + pair * (16 * 144) + k16 * 32);
                ldmx4(bl, bBaseL + pair * (16 * 144) + k16 * 32);
#pragma unroll
                for (int mt = 0; mt < 2; ++mt) {
                    mma_f16(C[mt][2 * pair],     ah[mt], bh[0], bh[1]);
                    mma_f16(C[mt][2 * pair],     ah[mt], bl[0], bl[1]);
                    mma_f16(C[mt][2 * pair + 1], ah[mt], bh[2], bh[3]);
                    mma_f16(C[mt][2 * pair + 1], ah[mt], bl[2], bl[3]);
                }
            }
        }
        __syncthreads();
    }

    // ---- epilogue: bias add, fp16 store ----
    const float* bias = (const float*)(sm + SBIAS_B);
#pragma unroll
    for (int mt = 0; mt < 2; ++mt) {
        int r0 = m0 + wm * 32 + mt * 16 + g;
        int r1 = r0 + 8;
#pragma unroll
        for (int nt = 0; nt < 8; ++nt) {
            int c = wn * 64 + nt * 8 + tig * 2;        // local col, even
            float bz0 = bias[c], bz1 = bias[c + 1];
            if (r0 < EE)
                *(__half2*)(g_EWh + (size_t)r0 * DSQ + n0 + c) =
                    __floats2half2_rn(C[mt][nt][0] + bz0, C[mt][nt][1] + bz1);
            if (r1 < EE)
                *(__half2*)(g_EWh + (size_t)r1 * DSQ + n0 + c) =
                    __floats2half2_rn(C[mt][nt][2] + bz0, C[mt][nt][3] + bz1);
        }
    }
}

// ---------------- per-layer: msg = h[src] @ EW[e] (fp16), scatter-add into aggr ---------
__global__ void conv_msg_kernel(const int* __restrict__ ei) {
    __shared__ float sh[8][64];
    int sub = threadIdx.x >> 5;                        // 8 edges / block, 1 warp each
    int t = threadIdx.x & 31;
    int e = blockIdx.x * 8 + sub;
    if (e >= EE) return;
    int src = ei[e];
    int dst = ei[EE + e];
    sh[sub][t] = g_h[src * DD + t];
    sh[sub][32 + t] = g_h[src * DD + 32 + t];
    __syncwarp();
    const __half2* ew2 = (const __half2*)(g_EWh + (size_t)e * DSQ) + t;
    float a0 = 0.f, a1 = 0.f;
#pragma unroll
    for (int d = 0; d < 64; ++d) {
        float2 w = __half22float2(ew2[d * 32]);
        float hv = sh[sub][d];
        a0 += hv * w.x;
        a1 += hv * w.y;
    }
    atomicAdd(&g_aggr[dst * DD + 2 * t], a0);
    atomicAdd(&g_aggr[dst * DD + 2 * t + 1], a1);
}

// ---------------- per-layer: h += aggr + h@root[l] + bias[l]; re-zero aggr ----------------
__global__ void h_update_kernel(const float* __restrict__ root_l,
                                const float* __restrict__ bias_l) {
    __shared__ float sh[4][64];
    int sub = threadIdx.x >> 6;
    int f = threadIdx.x & 63;
    int n = blockIdx.x * 4 + sub;
    sh[sub][f] = g_h[n * DD + f];
    __syncthreads();
    float acc = 0.f;
#pragma unroll 16
    for (int d = 0; d < 64; ++d) acc += sh[sub][d] * root_l[d * DD + f];
    g_h[n * DD + f] = sh[sub][f] + g_aggr[n * DD + f] + acc + bias_l[f];
    g_aggr[n * DD + f] = 0.f;
}

// ================= fused Set2Set (M steps of LSTM+escore+pool) + output MLP ==============
// One block per graph; all state lives in smem. 256 threads.
__global__ void __launch_bounds__(256) set2set_out_kernel(
    const float* __restrict__ Wih, const float* __restrict__ Whh,
    const float* __restrict__ bvec,
    const float* __restrict__ Wo1, const float* __restrict__ bo1,
    const float* __restrict__ Wo2, const float* __restrict__ bo2,
    float* __restrict__ out) {
    int b = blockIdx.x, t = threadIdx.x;
    int warp = t >> 5, lane = t & 31;
    __shared__ float sq[128], shh[64], scs[64], gs[256], red[256], r2[256];
    const int s = g_segstart[b], e = g_segstart[b + 1];

    if (t < 128) sq[t] = 0.f;
    if (t < 64) { shh[t] = 0.f; scs[t] = 0.f; }
    __syncthreads();

    for (int m = 0; m < MM; ++m) {
        // ---- LSTM gates ----
        for (int gi = warp; gi < 256; gi += 8) {
            float acc = 0.f;
#pragma unroll
            for (int k = 0; k < 4; ++k) acc += sq[lane + k * 32] * Wih[gi * 128 + lane + k * 32];
#pragma unroll
            for (int k = 0; k < 2; ++k) acc += shh[lane + k * 32] * Whh[gi * 64 + lane + k * 32];
#pragma unroll
            for (int o = 16; o > 0; o >>= 1) acc += __shfl_down_sync(0xffffffffu, acc, o);
            if (lane == 0) gs[gi] = acc + bvec[gi];
        }
        __syncthreads();
        if (t < 64) {
            float gi = gs[t], gf = gs[64 + t], gg = gs[128 + t], go = gs[192 + t];
            float c = sigf(gf) * scs[t] + sigf(gi) * tanhf(gg);
            scs[t] = c;
            shh[t] = sigf(go) * tanhf(c);
        }
        __syncthreads();
        // ---- escore: e[n] = h[n] . q ----
        for (int n = s + warp; n < e; n += 8) {
            float acc = g_h[n * 64 + lane] * shh[lane] + g_h[n * 64 + 32 + lane] * shh[32 + lane];
#pragma unroll
            for (int o = 16; o > 0; o >>= 1) acc += __shfl_down_sync(0xffffffffu, acc, o);
            if (lane == 0) g_escore[n] = acc;
        }
        __syncthreads();
        // ---- pool: per-graph softmax, r = sum a*h ----
        float mx = -3.4e38f;
        for (int n = s + t; n < e; n += 256) mx = fmaxf(mx, g_escore[n]);
        red[t] = mx;
        __syncthreads();
        for (int o = 128; o > 0; o >>= 1) { if (t < o) red[t] = fmaxf(red[t], red[t + o]); __syncthreads(); }
        mx = red[0];
        __syncthreads();
        float den = 0.f;
        for (int n = s + t; n < e; n += 256) den += expf(g_escore[n] - mx);
        red[t] = den;
        __syncthreads();
        for (int o = 128; o > 0; o >>= 1) { if (t < o) red[t] += red[t + o]; __syncthreads(); }
        float inv = (e > s) ? (1.f / red[0]) : 0.f;
        __syncthreads();
        int f = t & 63, grp = t >> 6;
        float rf = 0.f;
        for (int n = s + grp; n < e; n += 4) rf += expf(g_escore[n] - mx) * g_h[n * 64 + f];
        r2[t] = rf;
        __syncthreads();
        if (t < 64) {
            float rv = (r2[t] + r2[64 + t] + r2[128 + t] + r2[192 + t]) * inv;
            sq[t] = shh[t];
            sq[64 + t] = rv;
        }
        __syncthreads();
    }
    // ---- out = silu(q_star @ Wo1 + bo1) @ Wo2 + bo2 ----
    if (t < 64) {
        float acc = bo1[t];
#pragma unroll 16
        for (int k = 0; k < 128; ++k) acc += sq[k] * Wo1[k * 64 + t];
        float sv = acc * sigf(acc);
        red[t] = sv * Wo2[t];
    }
    __syncthreads();
    for (int o = 32; o > 0; o >>= 1) { if (t < o) red[t] += red[t + o]; __syncthreads(); }
    if (t == 0) out[b] = red[0] + bo2[0];
}

// ---------------- launch ----------------
extern "C" void kernel_launch(void* const* d_in, const int* in_sizes, int n_in,
                              void* d_out, int out_size) {
    const float* x         = (const float*)d_in[0];
    const int*   edgeidx   = (const int*)d_in[1];
    const float* edge_attr = (const float*)d_in[2];
    const int*   batch     = (const int*)d_in[3];
    const float* W0        = (const float*)d_in[4];
    const float* b0        = (const float*)d_in[5];
    const float* Wn1       = (const float*)d_in[6];
    const float* bn1       = (const float*)d_in[7];
    const float* Wn2       = (const float*)d_in[8];
    const float* bn2       = (const float*)d_in[9];
    const float* root      = (const float*)d_in[10];
    const float* conv_bias = (const float*)d_in[11];
    const float* lstm_Wih  = (const float*)d_in[12];
    const float* lstm_Whh  = (const float*)d_in[13];
    const float* lstm_b    = (const float*)d_in[14];
    const float* Wo1       = (const float*)d_in[15];
    const float* bo1       = (const float*)d_in[16];
    const float* Wo2       = (const float*)d_in[17];
    const float* bo2       = (const float*)d_in[18];
    float* out = (float*)d_out;

    cudaFuncSetAttribute(ew_gemm_mma, cudaFuncAttributeMaxDynamicSharedMemorySize,
                         EW_SMEM_BYTES);

    prologue_kernel<<<(EE * DH + 255) / 256, 256>>>(x, edge_attr, batch, W0, b0,
                                                    Wn1, bn1, Wn2);

    dim3 ggrid(32, (EE + 127) / 128);                  // 32 n-blocks x 313 m-blocks
    ew_gemm_mma<<<ggrid, 256, EW_SMEM_BYTES>>>(bn2);

    for (int l = 0; l < LL; ++l) {
        conv_msg_kernel<<<(EE + 7) / 8, 256>>>(edgeidx);
        h_update_kernel<<<(NN + 3) / 4, 256>>>(root + (size_t)l * DSQ, conv_bias + l * DD);
    }

    set2set_out_kernel<<<BB, 256>>>(lstm_Wih, lstm_Whh, lstm_b, Wo1, bo1, Wo2, bo2, out);
}